// round 1
// baseline (speedup 1.0000x reference)
#include <cuda_runtime.h>
#include <cstdint>

// Problem constants (fixed by reference)
#define RDIM 4096
#define TLEN 2048
#define IDIM 8
#define ODIM 8
#define MAXNNZ 640            // Binomial(4096,0.1): mean 410, sd 19 -> 640 is ~+12 sd, safe
#define NBLK 128              // persistent CTAs, <= 148 SMs -> wave-1 co-resident
#define NTHR 256
#define ROWS_PER_CTA (RDIM / NBLK)      // 32
#define ROWS_PER_WARP (ROWS_PER_CTA / 8) // 4

struct __align__(8) Ent { float v; int c; };

// Scratch (device globals: no allocation allowed)
__device__ Ent      g_ell[RDIM * MAXNNZ];   // ~20 MB
__device__ int      g_cnt[RDIM];
__device__ float    g_u[TLEN * RDIM];       // 32 MB: Win @ x_t for all t
__device__ float    g_h[2][RDIM];           // ping-pong hidden state
__device__ unsigned g_bar;                  // grid barrier counter

// ---------------------------------------------------------------------------
// K1: u[t][r] = sum_i Win[r,i] * x[t,i]
// ---------------------------------------------------------------------------
__global__ void k_u(const float* __restrict__ x, const float* __restrict__ Win) {
    int t = blockIdx.x;
    __shared__ float xs[IDIM];
    if (threadIdx.x < IDIM) xs[threadIdx.x] = x[t * IDIM + threadIdx.x];
    __syncthreads();
    for (int r = threadIdx.x; r < RDIM; r += blockDim.x) {
        const float4* w = (const float4*)(Win + r * IDIM);
        float4 a = __ldg(&w[0]), b = __ldg(&w[1]);
        float s = a.x * xs[0] + a.y * xs[1] + a.z * xs[2] + a.w * xs[3]
                + b.x * xs[4] + b.y * xs[5] + b.z * xs[6] + b.w * xs[7];
        g_u[t * RDIM + r] = s;
    }
}

// ---------------------------------------------------------------------------
// K2: compact W rows into ELL. One warp per row; ballot/popc stream compaction.
// Zeros in W are exact (mask multiply), so v != 0 identifies nonzeros.
// ---------------------------------------------------------------------------
__global__ void k_sparse(const float* __restrict__ W) {
    int warp = (blockIdx.x * blockDim.x + threadIdx.x) >> 5;
    int lane = threadIdx.x & 31;
    if (warp >= RDIM) return;
    const float* wr = W + (size_t)warp * RDIM;
    int cnt = 0;
    for (int c0 = 0; c0 < RDIM; c0 += 32) {
        float v = wr[c0 + lane];
        unsigned bal = __ballot_sync(0xffffffffu, v != 0.0f);
        if (v != 0.0f) {
            int pos = cnt + __popc(bal & ((1u << lane) - 1u));
            if (pos < MAXNNZ) {
                g_ell[warp * MAXNNZ + pos].v = v;
                g_ell[warp * MAXNNZ + pos].c = c0 + lane;
            }
        }
        cnt += __popc(bal);
    }
    if (lane == 0) g_cnt[warp] = cnt < MAXNNZ ? cnt : MAXNNZ;
}

// ---------------------------------------------------------------------------
// K3: per-replay init. Zero h buffers, reset barrier, seed out with bias.
// ---------------------------------------------------------------------------
__global__ void k_init(float* __restrict__ out, const float* __restrict__ bias) {
    int i = blockIdx.x * blockDim.x + threadIdx.x;
    if (i < 2 * RDIM) ((float*)g_h)[i] = 0.0f;
    if (i < TLEN * ODIM) out[i] = bias[i & (ODIM - 1)];
    if (i == 0) g_bar = 0u;
}

// ---------------------------------------------------------------------------
// K4: persistent recurrence. 128 CTAs x 256 threads, 32 rows/CTA (L1-resident
// ELL slice), grid barrier per step.
// ---------------------------------------------------------------------------
__global__ void __launch_bounds__(NTHR, 1)
k_main(const float* __restrict__ Wout, float* __restrict__ out) {
    __shared__ float sh[RDIM];          // 16 KB: h_{t-1}
    __shared__ float ybuf[8][ODIM];

    const int tid  = threadIdx.x;
    const int wid  = tid >> 5;
    const int lane = tid & 31;
    const int row0 = blockIdx.x * ROWS_PER_CTA + wid * ROWS_PER_WARP;
    const unsigned G = gridDim.x;

    // Hoist per-row metadata out of the time loop (fixed across steps)
    int cnts[ROWS_PER_WARP];
    const Ent* eptr[ROWS_PER_WARP];
#pragma unroll
    for (int rr = 0; rr < ROWS_PER_WARP; rr++) {
        cnts[rr] = g_cnt[row0 + rr];
        eptr[rr] = g_ell + (size_t)(row0 + rr) * MAXNNZ;
    }

    for (int t = 0; t < TLEN; ++t) {
        const float* hp = g_h[t & 1];
        float* hn = g_h[(t + 1) & 1];

        // Stage h_{t-1} into SMEM, bypassing L1 (other CTAs wrote it)
        for (int i = tid * 4; i < RDIM; i += NTHR * 4) {
            float4 v = __ldcg((const float4*)(hp + i));
            *(float4*)(sh + i) = v;
        }
        __syncthreads();

        float yacc[ODIM];
#pragma unroll
        for (int o = 0; o < ODIM; o++) yacc[o] = 0.0f;

#pragma unroll
        for (int rr = 0; rr < ROWS_PER_WARP; rr++) {
            const int   row = row0 + rr;
            const int   cnt = cnts[rr];
            const Ent*  e   = eptr[rr];
            float acc = 0.0f;
            for (int k = lane; k < cnt; k += 32) {
                Ent en = e[k];                 // LDG.64, L1-resident
                acc += en.v * sh[en.c];        // SMEM gather
            }
#pragma unroll
            for (int s = 16; s; s >>= 1)
                acc += __shfl_xor_sync(0xffffffffu, acc, s);
            if (lane == 0) {
                float hv = tanhf(acc + __ldg(&g_u[t * RDIM + row]));
                __stcg(hn + row, hv);          // bypass L1 on the way out
#pragma unroll
                for (int o = 0; o < ODIM; o++)
                    yacc[o] += hv * __ldg(&Wout[o * RDIM + row]);
            }
        }

        // Reduce y partials across the CTA's 8 warps, one atomicAdd per output
        if (lane == 0) {
#pragma unroll
            for (int o = 0; o < ODIM; o++) ybuf[wid][o] = yacc[o];
        }
        __syncthreads();
        if (tid < ODIM) {
            float s = 0.0f;
#pragma unroll
            for (int w = 0; w < 8; w++) s += ybuf[w][tid];
            atomicAdd(out + t * ODIM + tid, s);
        }

        // Grid barrier: release h_next writes, wait for all CTAs
        __threadfence();
        __syncthreads();
        if (tid == 0) {
            atomicAdd(&g_bar, 1u);
            const unsigned target = (unsigned)(t + 1) * G;
            unsigned v;
            do {
                asm volatile("ld.acquire.gpu.global.u32 %0, [%1];"
                             : "=r"(v) : "l"(&g_bar));
            } while (v < target);
        }
        __syncthreads();
    }
}

// ---------------------------------------------------------------------------
extern "C" void kernel_launch(void* const* d_in, const int* in_sizes, int n_in,
                              void* d_out, int out_size) {
    (void)in_sizes; (void)n_in; (void)out_size;
    const float* x      = (const float*)d_in[0];  // [1, 2048, 8]
    const float* Win    = (const float*)d_in[1];  // [4096, 8]
    const float* W      = (const float*)d_in[2];  // [4096, 4096]
    const float* Wout_w = (const float*)d_in[3];  // [8, 4096]
    const float* Wout_b = (const float*)d_in[4];  // [8]
    float* out = (float*)d_out;                   // [1, 2048, 8]

    k_u<<<TLEN, NTHR>>>(x, Win);
    k_sparse<<<(RDIM * 32 + NTHR - 1) / NTHR, NTHR>>>(W);
    k_init<<<(TLEN * ODIM + NTHR - 1) / NTHR, NTHR>>>(out, Wout_b);
    k_main<<<NBLK, NTHR>>>(Wout_w, out);
}